// round 2
// baseline (speedup 1.0000x reference)
#include <cuda_runtime.h>
#include <math.h>

// Shapes (fixed by the problem)
#define NSENT 4096
#define L     512
#define LQ    32
#define D     30
#define AF    10
#define KK    4

// Precomputed tables / question-side results
__device__ float g_W1sum[D][D];
__device__ float g_W2sum[D][D];
__device__ float g_A1[D][D][6];     // boundary coefficient tensor from conv1_w
__device__ float g_qraw[D];          // question column sums (cos is scale invariant)
__device__ float g_q1g[D];
__device__ float g_q2g[D];
__device__ float g_inv_nraw, g_inv_n1, g_inv_n2;
__device__ float g_costs[NSENT];

// ---------------------------------------------------------------------------
// Kernel 1: weight precompute + full question side (single warp)
// ---------------------------------------------------------------------------
__global__ void prep_kernel(const float* __restrict__ qe,
                            const float* __restrict__ w1, const float* __restrict__ b1,
                            const float* __restrict__ w2, const float* __restrict__ b2)
{
    int tid = threadIdx.x; // 32 threads

    for (int idx = tid; idx < D * D; idx += 32) {
        int o = idx / D, j = idx % D;
        const float* w = w1 + idx * KK;
        float w0 = w[0], wv1 = w[1], wv2 = w[2], w3 = w[3];
        g_W1sum[o][j] = w0 + wv1 + wv2 + w3;
        const float* v = w2 + idx * KK;
        g_W2sum[o][j] = v[0] + v[1] + v[2] + v[3];
        // deficit-weighted boundary taps (deficits 3,2,1 | 1,2,3)
        g_A1[o][j][0] = 3.f * w3 + 2.f * wv2 + wv1;  // x[.,0]
        g_A1[o][j][1] = 2.f * w3 + wv2;              // x[.,1]
        g_A1[o][j][2] = w3;                          // x[.,2]
        g_A1[o][j][3] = w0;                          // x[.,L-3]
        g_A1[o][j][4] = 2.f * w0 + wv1;              // x[.,L-2]
        g_A1[o][j][5] = 3.f * w0 + 2.f * wv1 + wv2;  // x[.,L-1]
    }
    __syncthreads();

    __shared__ float Sq[D], xbq[6][D], q1g_s[D], Tq[D], q2g_s[D];
    for (int j = tid; j < D; j += 32) {
        float s = 0.f;
        for (int t = 0; t < LQ; t++) s += qe[t * D + j];
        Sq[j] = s;
        xbq[0][j] = qe[0 * D + j];
        xbq[1][j] = qe[1 * D + j];
        xbq[2][j] = qe[2 * D + j];
        xbq[3][j] = qe[(LQ - 3) * D + j];
        xbq[4][j] = qe[(LQ - 2) * D + j];
        xbq[5][j] = qe[(LQ - 1) * D + j];
    }
    __syncthreads();

    const float invLq3 = 1.f / (float)(LQ + 3);
    for (int o = tid; o < D; o += 32) {
        float ds = 0.f, bc = 0.f;
        for (int j = 0; j < D; j++) ds += g_W1sum[o][j] * Sq[j];
        for (int j = 0; j < D; j++) {
            #pragma unroll
            for (int m = 0; m < 6; m++) bc += g_A1[o][j][m] * xbq[m][j];
        }
        q1g_s[o] = b1[o] + ds * invLq3;
        Tq[o] = (float)LQ * b1[o] + ds - 0.25f * bc;
    }
    __syncthreads();
    for (int o = tid; o < D; o += 32) {
        float d2 = 0.f;
        for (int j = 0; j < D; j++) d2 += g_W2sum[o][j] * Tq[j];
        q2g_s[o] = b2[o] + d2 * invLq3;
        g_qraw[o] = Sq[o];
        g_q1g[o] = q1g_s[o];
        g_q2g[o] = q2g_s[o];
    }
    __syncthreads();
    if (tid == 0) {
        float n0 = 0.f, n1 = 0.f, n2 = 0.f;
        for (int j = 0; j < D; j++) {
            n0 += Sq[j] * Sq[j];
            n1 += q1g_s[j] * q1g_s[j];
            n2 += q2g_s[j] * q2g_s[j];
        }
        g_inv_nraw = rsqrtf(n0);
        g_inv_n1 = rsqrtf(n1);
        g_inv_n2 = rsqrtf(n2);
    }
}

// ---------------------------------------------------------------------------
// Kernel 2: one block per sentence — streaming column-sum + tiny math tail
// ---------------------------------------------------------------------------
#define TPB 480   // multiple of 15 -> fixed channel phase per thread for float4s

__global__ __launch_bounds__(TPB) void sent_kernel(
    const float* __restrict__ se, const float* __restrict__ gaf,
    const int* __restrict__ labels,
    const float* __restrict__ b1, const float* __restrict__ b2,
    const float* __restrict__ lw, const float* __restrict__ lb,
    float* __restrict__ out)
{
    const int n = blockIdx.x;
    const int tid = threadIdx.x;

    __shared__ float S[D];
    __shared__ float xb[6][D];
    __shared__ float s1g[32], T[32];

    if (tid < D) S[tid] = 0.f;
    if (tid < 6 * D) {
        int m = tid / D, j = tid % D;
        int t = (m < 3) ? m : (L - 6 + m);  // 0,1,2,509,510,511
        xb[m][j] = se[(size_t)n * (L * D) + (size_t)t * D + j];
    }
    __syncthreads();

    // Stream the [512,30] tile as 3840 float4s. 480*4 % 30 == 0 => each
    // thread's 4 lanes always hit the same 4 channels.
    const float4* p = reinterpret_cast<const float4*>(se) + (size_t)n * (L * D / 4);
    float a0 = 0.f, a1 = 0.f, a2 = 0.f, a3 = 0.f;
    #pragma unroll
    for (int it = 0; it < (L * D / 4) / TPB; it++) {
        float4 v = p[tid + TPB * it];
        a0 += v.x; a1 += v.y; a2 += v.z; a3 += v.w;
    }
    int jb = (4 * tid) % D;
    atomicAdd(&S[jb], a0);
    atomicAdd(&S[(jb + 1) % D], a1);
    atomicAdd(&S[(jb + 2) % D], a2);
    atomicAdd(&S[(jb + 3) % D], a3);
    __syncthreads();

    if (tid < 32) {
        const int o = tid;
        const float inv515 = 1.f / (float)(L + 3);
        float s1 = 0.f, Tv = 0.f;
        if (o < D) {
            float ds = 0.f, bc = 0.f;
            for (int j = 0; j < D; j++) ds += g_W1sum[o][j] * S[j];
            for (int j = 0; j < D; j++) {
                #pragma unroll
                for (int m = 0; m < 6; m++) bc += g_A1[o][j][m] * xb[m][j];
            }
            s1 = b1[o] + ds * inv515;
            Tv = (float)L * b1[o] + ds - 0.25f * bc;
        }
        s1g[o] = s1; T[o] = Tv;
        __syncwarp();

        float s2 = 0.f;
        if (o < D) {
            float d2 = 0.f;
            for (int j = 0; j < D; j++) d2 += g_W2sum[o][j] * T[j];
            s2 = b2[o] + d2 * inv515;
        }

        float Sv = 0.f, qr = 0.f, q1v = 0.f, q2v = 0.f;
        if (o < D) { Sv = S[o]; qr = g_qraw[o]; q1v = g_q1g[o]; q2v = g_q2g[o]; }

        float p0 = Sv * qr;    // dot(S, q_raw)
        float p1 = Sv * q2v;   // dot(S, q2g)
        float p2 = Sv * Sv;    // |S|^2
        float p3 = s1 * q1v;   // dot(s1g, q1g)
        float p4 = s1 * s1;
        float p5 = s2 * q2v;   // dot(s2g, q2g)
        float p6 = s2 * s2;
        #pragma unroll
        for (int off = 16; off; off >>= 1) {
            p0 += __shfl_down_sync(0xffffffffu, p0, off);
            p1 += __shfl_down_sync(0xffffffffu, p1, off);
            p2 += __shfl_down_sync(0xffffffffu, p2, off);
            p3 += __shfl_down_sync(0xffffffffu, p3, off);
            p4 += __shfl_down_sync(0xffffffffu, p4, off);
            p5 += __shfl_down_sync(0xffffffffu, p5, off);
            p6 += __shfl_down_sync(0xffffffffu, p6, off);
        }
        if (o == 0) {
            float inv_nS = rsqrtf(p2);
            float sim1 = (n == 0) ? (p0 * g_inv_nraw * inv_nS)
                                  : (p1 * g_inv_n2 * inv_nS);
            float sim2 = p3 * rsqrtf(p4) * g_inv_n1;
            float sim3 = p5 * rsqrtf(p6) * g_inv_n2;

            const float* g = gaf + (size_t)n * AF;
            float l0 = lb[0] + lw[0] * sim1 + lw[1] * sim2 + lw[2] * sim3;
            float l1 = lb[1] + lw[13] * sim1 + lw[14] * sim2 + lw[15] * sim3;
            #pragma unroll
            for (int f = 0; f < AF; f++) {
                float gv = g[f];
                l0 += lw[3 + f] * gv;
                l1 += lw[16 + f] * gv;
            }
            float mx = fmaxf(l0, l1);
            float lse = mx + logf(expf(l0 - mx) + expf(l1 - mx));
            float lp0 = l0 - lse, lp1 = l1 - lse;
            float e0 = expf(lp0), e1 = expf(lp1);
            out[1 + n] = e1 / (e0 + e1);        // softmax(log_softmax)[1]
            int lab = labels[n];
            g_costs[n] = -(lab ? lp1 : lp0);
        }
    }
}

// ---------------------------------------------------------------------------
// Kernel 3: deterministic cost reduction
// ---------------------------------------------------------------------------
__global__ void final_kernel(float* __restrict__ out)
{
    __shared__ float sm[256];
    float s = 0.f;
    for (int i = threadIdx.x; i < NSENT; i += 256) s += g_costs[i];
    sm[threadIdx.x] = s;
    __syncthreads();
    for (int w = 128; w; w >>= 1) {
        if (threadIdx.x < w) sm[threadIdx.x] += sm[threadIdx.x + w];
        __syncthreads();
    }
    if (threadIdx.x == 0) out[0] = sm[0] / (float)NSENT;
}

// ---------------------------------------------------------------------------
extern "C" void kernel_launch(void* const* d_in, const int* in_sizes, int n_in,
                              void* d_out, int out_size)
{
    const float* se  = (const float*)d_in[0];  // sents_embeds [N,L,D]
    const float* qe  = (const float*)d_in[1];  // question_embeds [LQ,D]
    const float* gaf = (const float*)d_in[2];  // [N,AF]
    const int*   lab = (const int*)d_in[3];    // [N]
    const float* w1  = (const float*)d_in[4];
    const float* b1  = (const float*)d_in[5];
    const float* w2  = (const float*)d_in[6];
    const float* b2  = (const float*)d_in[7];
    const float* lw  = (const float*)d_in[8];  // [2,13]
    const float* lb  = (const float*)d_in[9];  // [2]
    float* out = (float*)d_out;                // [0]=cost, [1..N]=emit

    prep_kernel<<<1, 32>>>(qe, w1, b1, w2, b2);
    sent_kernel<<<NSENT, TPB>>>(se, gaf, lab, b1, b2, lw, lb, out);
    final_kernel<<<1, 256>>>(out);
}

// round 3
// speedup vs baseline: 1.0080x; 1.0080x over previous
#include <cuda_runtime.h>
#include <math.h>

// Shapes (fixed by the problem)
#define NSENT 4096
#define L     512
#define LQ    32
#define D     30
#define AF    10
#define KK    4

// Precomputed tables / question-side results
__device__ float g_W1sum[D * D];
__device__ float g_W2sum[D * D];
__device__ float g_A1[D * D * 6];   // boundary coefficient tensor from conv1_w
__device__ float g_qraw[D];
__device__ float g_q1g[D];
__device__ float g_q2g[D];
__device__ float g_inv_nraw, g_inv_n1, g_inv_n2;
__device__ float g_S[NSENT][D];     // per-sentence column sums
__device__ float g_costs[NSENT];
__device__ int   g_ctr;

// ---------------------------------------------------------------------------
// Kernel 1 (prep): tables with 900 threads, question side with warp 0
// ---------------------------------------------------------------------------
__global__ void prep_kernel(const float* __restrict__ qe,
                            const float* __restrict__ w1, const float* __restrict__ b1,
                            const float* __restrict__ w2, const float* __restrict__ b2)
{
    int tid = threadIdx.x; // 960 threads

    if (tid == 0) g_ctr = 0;

    if (tid < D * D) {
        const float* w = w1 + tid * KK;
        float w0 = w[0], wv1 = w[1], wv2 = w[2], w3 = w[3];
        g_W1sum[tid] = w0 + wv1 + wv2 + w3;
        const float* v = w2 + tid * KK;
        g_W2sum[tid] = v[0] + v[1] + v[2] + v[3];
        float* A = g_A1 + tid * 6;
        A[0] = 3.f * w3 + 2.f * wv2 + wv1;  // x[.,0]
        A[1] = 2.f * w3 + wv2;              // x[.,1]
        A[2] = w3;                          // x[.,2]
        A[3] = w0;                          // x[.,LQ-3]
        A[4] = 2.f * w0 + wv1;              // x[.,LQ-2]
        A[5] = 3.f * w0 + 2.f * wv1 + wv2;  // x[.,LQ-1]
    }

    __shared__ float Sq[32], xbq[6][32], q1g_s[32], Tq[32], q2g_s[32];
    if (tid < D) {
        float s = 0.f;
        for (int t = 0; t < LQ; t++) s += qe[t * D + tid];
        Sq[tid] = s;
        xbq[0][tid] = qe[0 * D + tid];
        xbq[1][tid] = qe[1 * D + tid];
        xbq[2][tid] = qe[2 * D + tid];
        xbq[3][tid] = qe[(LQ - 3) * D + tid];
        xbq[4][tid] = qe[(LQ - 2) * D + tid];
        xbq[5][tid] = qe[(LQ - 1) * D + tid];
    }
    __syncthreads();   // tables in gmem + Sq/xbq in smem visible

    if (tid < 32) {
        const int o = tid;
        const float invLq3 = 1.f / (float)(LQ + 3);
        float q1 = 0.f, Tv = 0.f;
        if (o < D) {
            float ds = 0.f, bc = 0.f;
            for (int j = 0; j < D; j++) ds += g_W1sum[o * D + j] * Sq[j];
            for (int j = 0; j < D; j++) {
                const float* A = g_A1 + (o * D + j) * 6;
                #pragma unroll
                for (int m = 0; m < 6; m++) bc += A[m] * xbq[m][j];
            }
            q1 = b1[o] + ds * invLq3;
            Tv = (float)LQ * b1[o] + ds - 0.25f * bc;
        }
        q1g_s[o] = q1; Tq[o] = Tv;
        __syncwarp();

        float q2 = 0.f;
        if (o < D) {
            float d2 = 0.f;
            for (int j = 0; j < D; j++) d2 += g_W2sum[o * D + j] * Tq[j];
            q2 = b2[o] + d2 * invLq3;
            g_qraw[o] = Sq[o];
            g_q1g[o] = q1;
            g_q2g[o] = q2;
        }
        q2g_s[o] = q2;
        __syncwarp();

        // norms via warp reduction
        float n0 = (o < D) ? Sq[o] * Sq[o] : 0.f;
        float n1 = q1 * q1;
        float n2 = q2 * q2;
        #pragma unroll
        for (int off = 16; off; off >>= 1) {
            n0 += __shfl_down_sync(0xffffffffu, n0, off);
            n1 += __shfl_down_sync(0xffffffffu, n1, off);
            n2 += __shfl_down_sync(0xffffffffu, n2, off);
        }
        if (o == 0) {
            g_inv_nraw = rsqrtf(n0);
            g_inv_n1 = rsqrtf(n1);
            g_inv_n2 = rsqrtf(n2);
        }
    }
}

// ---------------------------------------------------------------------------
// Kernel A: pure streaming column-sum. One block per sentence.
// ---------------------------------------------------------------------------
#define TPB 480   // 480*4 % 30 == 0 -> fixed channel phase per thread

__global__ __launch_bounds__(TPB, 4) void colsum_kernel(const float* __restrict__ se)
{
    const int n = blockIdx.x;
    const int tid = threadIdx.x;

    __shared__ float S[D];
    if (tid < D) S[tid] = 0.f;

    const float4* p = reinterpret_cast<const float4*>(se) + (size_t)n * (L * D / 4);
    float a0 = 0.f, a1 = 0.f, a2 = 0.f, a3 = 0.f;
    #pragma unroll
    for (int it = 0; it < (L * D / 4) / TPB; it++) {
        float4 v = __ldcs(p + tid + TPB * it);
        a0 += v.x; a1 += v.y; a2 += v.z; a3 += v.w;
    }
    __syncthreads();
    int jb = (4 * tid) % D;
    atomicAdd(&S[jb], a0);
    atomicAdd(&S[(jb + 1) % D], a1);
    atomicAdd(&S[(jb + 2) % D], a2);
    atomicAdd(&S[(jb + 3) % D], a3);
    __syncthreads();
    if (tid < D) g_S[n][tid] = S[tid];
}

// ---------------------------------------------------------------------------
// Kernel B: per-sentence tail math, 1 warp/sentence, tables staged in smem.
// Last block folds the deterministic cost reduction.
// ---------------------------------------------------------------------------
#define TAIL_TPB 128
#define TAIL_BLOCKS (NSENT / 4)

__global__ __launch_bounds__(TAIL_TPB) void tail_kernel(
    const float* __restrict__ se, const float* __restrict__ gaf,
    const int* __restrict__ labels,
    const float* __restrict__ b1, const float* __restrict__ b2,
    const float* __restrict__ lw, const float* __restrict__ lb,
    float* __restrict__ out)
{
    __shared__ float sW1[D * D], sW2[D * D], sA1[D * D * 6];
    __shared__ float scr[4][8][32];  // per-warp: [0]=S, [1..6]=xb, [7]=T
    __shared__ int last;

    const int tid = threadIdx.x;
    for (int i = tid; i < D * D; i += TAIL_TPB) { sW1[i] = g_W1sum[i]; sW2[i] = g_W2sum[i]; }
    for (int i = tid; i < D * D * 6; i += TAIL_TPB) sA1[i] = g_A1[i];
    __syncthreads();

    const int w = tid / 32, o = tid % 32;
    const int n = blockIdx.x * 4 + w;

    float Sv = 0.f;
    if (o < D) {
        Sv = g_S[n][o];
        const float* base = se + (size_t)n * (L * D);
        scr[w][1][o] = base[0 * D + o];
        scr[w][2][o] = base[1 * D + o];
        scr[w][3][o] = base[2 * D + o];
        scr[w][4][o] = base[(L - 3) * D + o];
        scr[w][5][o] = base[(L - 2) * D + o];
        scr[w][6][o] = base[(L - 1) * D + o];
    }
    scr[w][0][o] = Sv;
    __syncwarp();

    const float inv515 = 1.f / (float)(L + 3);
    float s1 = 0.f, Tv = 0.f;
    if (o < D) {
        float ds = 0.f, bc = 0.f;
        for (int j = 0; j < D; j++) ds += sW1[o * D + j] * scr[w][0][j];
        for (int j = 0; j < D; j++) {
            const float* A = sA1 + (o * D + j) * 6;
            #pragma unroll
            for (int m = 0; m < 6; m++) bc += A[m] * scr[w][1 + m][j];
        }
        s1 = b1[o] + ds * inv515;
        Tv = (float)L * b1[o] + ds - 0.25f * bc;
    }
    scr[w][7][o] = Tv;
    __syncwarp();

    float s2 = 0.f;
    if (o < D) {
        float d2 = 0.f;
        for (int j = 0; j < D; j++) d2 += sW2[o * D + j] * scr[w][7][j];
        s2 = b2[o] + d2 * inv515;
    }

    float qr = 0.f, q1v = 0.f, q2v = 0.f;
    if (o < D) { qr = g_qraw[o]; q1v = g_q1g[o]; q2v = g_q2g[o]; }

    float p0 = Sv * qr, p1 = Sv * q2v, p2 = Sv * Sv;
    float p3 = s1 * q1v, p4 = s1 * s1, p5 = s2 * q2v, p6 = s2 * s2;
    #pragma unroll
    for (int off = 16; off; off >>= 1) {
        p0 += __shfl_down_sync(0xffffffffu, p0, off);
        p1 += __shfl_down_sync(0xffffffffu, p1, off);
        p2 += __shfl_down_sync(0xffffffffu, p2, off);
        p3 += __shfl_down_sync(0xffffffffu, p3, off);
        p4 += __shfl_down_sync(0xffffffffu, p4, off);
        p5 += __shfl_down_sync(0xffffffffu, p5, off);
        p6 += __shfl_down_sync(0xffffffffu, p6, off);
    }
    if (o == 0) {
        float inv_nS = rsqrtf(p2);
        float sim1 = (n == 0) ? (p0 * g_inv_nraw * inv_nS)
                              : (p1 * g_inv_n2 * inv_nS);
        float sim2 = p3 * rsqrtf(p4) * g_inv_n1;
        float sim3 = p5 * rsqrtf(p6) * g_inv_n2;

        const float* g = gaf + (size_t)n * AF;
        float l0 = lb[0] + lw[0] * sim1 + lw[1] * sim2 + lw[2] * sim3;
        float l1 = lb[1] + lw[13] * sim1 + lw[14] * sim2 + lw[15] * sim3;
        #pragma unroll
        for (int f = 0; f < AF; f++) {
            float gv = g[f];
            l0 += lw[3 + f] * gv;
            l1 += lw[16 + f] * gv;
        }
        float mx = fmaxf(l0, l1);
        float lse = mx + logf(expf(l0 - mx) + expf(l1 - mx));
        float lp0 = l0 - lse, lp1 = l1 - lse;
        float e0 = expf(lp0), e1 = expf(lp1);
        out[1 + n] = e1 / (e0 + e1);
        int lab = labels[n];
        g_costs[n] = -(lab ? lp1 : lp0);
    }

    // last block does the (deterministic) cost reduction
    __syncthreads();
    if (tid == 0) {
        __threadfence();
        int old = atomicAdd(&g_ctr, 1);
        last = (old == TAIL_BLOCKS - 1) ? 1 : 0;
    }
    __syncthreads();
    if (last) {
        __threadfence();
        __shared__ float sm[TAIL_TPB];
        float s = 0.f;
        for (int i = tid; i < NSENT; i += TAIL_TPB) s += g_costs[i];
        sm[tid] = s;
        __syncthreads();
        for (int ww = TAIL_TPB / 2; ww; ww >>= 1) {
            if (tid < ww) sm[tid] += sm[tid + ww];
            __syncthreads();
        }
        if (tid == 0) out[0] = sm[0] / (float)NSENT;
    }
}

// ---------------------------------------------------------------------------
extern "C" void kernel_launch(void* const* d_in, const int* in_sizes, int n_in,
                              void* d_out, int out_size)
{
    const float* se  = (const float*)d_in[0];  // sents_embeds [N,L,D]
    const float* qe  = (const float*)d_in[1];  // question_embeds [LQ,D]
    const float* gaf = (const float*)d_in[2];  // [N,AF]
    const int*   lab = (const int*)d_in[3];    // [N]
    const float* w1  = (const float*)d_in[4];
    const float* b1  = (const float*)d_in[5];
    const float* w2  = (const float*)d_in[6];
    const float* b2  = (const float*)d_in[7];
    const float* lw  = (const float*)d_in[8];  // [2,13]
    const float* lb  = (const float*)d_in[9];  // [2]
    float* out = (float*)d_out;                // [0]=cost, [1..N]=emit

    prep_kernel<<<1, 960>>>(qe, w1, b1, w2, b2);
    colsum_kernel<<<NSENT, TPB>>>(se);
    tail_kernel<<<TAIL_BLOCKS, TAIL_TPB>>>(se, gaf, lab, b1, b2, lw, lb, out);
}

// round 6
// speedup vs baseline: 1.5560x; 1.5436x over previous
#include <cuda_runtime.h>
#include <math.h>

// Shapes (fixed by the problem)
#define NSENT 4096
#define L     512
#define LQ    32
#define D     30
#define AF    10
#define KK    4

// Precomputed tables / question-side results
__device__ float g_W1sum[D * D];
__device__ float g_W2sum[D * D];
__device__ float g_A1[D * D * 6];   // boundary coefficient tensor from conv1_w
__device__ float g_qraw[D];
__device__ float g_q1g[D];
__device__ float g_q2g[D];
__device__ float g_inv_nraw, g_inv_n1, g_inv_n2;
__device__ float g_costs[NSENT];
__device__ int   g_ctr;

// ---------------------------------------------------------------------------
// Kernel 1 (prep): tables computed into SMEM (and mirrored to gmem);
// question-side serial phase reads SMEM only.
// ---------------------------------------------------------------------------
__global__ void prep_kernel(const float* __restrict__ qe,
                            const float* __restrict__ w1, const float* __restrict__ b1,
                            const float* __restrict__ w2, const float* __restrict__ b2)
{
    __shared__ float sW1[D * D], sW2[D * D], sA[D * D * 6];
    __shared__ float Sq[32], xbq[6][32], Tq[32];

    int tid = threadIdx.x; // 960 threads
    if (tid == 0) g_ctr = 0;

    if (tid < D * D) {
        const float* w = w1 + tid * KK;
        float w0 = w[0], wv1 = w[1], wv2 = w[2], w3 = w[3];
        float ws = w0 + wv1 + wv2 + w3;
        sW1[tid] = ws; g_W1sum[tid] = ws;
        const float* v = w2 + tid * KK;
        float vs = v[0] + v[1] + v[2] + v[3];
        sW2[tid] = vs; g_W2sum[tid] = vs;
        float a0 = 3.f * w3 + 2.f * wv2 + wv1;
        float a1 = 2.f * w3 + wv2;
        float a2 = w3;
        float a3 = w0;
        float a4 = 2.f * w0 + wv1;
        float a5 = 3.f * w0 + 2.f * wv1 + wv2;
        float* As = sA + tid * 6;  float* Ag = g_A1 + tid * 6;
        As[0] = a0; Ag[0] = a0;  As[1] = a1; Ag[1] = a1;
        As[2] = a2; Ag[2] = a2;  As[3] = a3; Ag[3] = a3;
        As[4] = a4; Ag[4] = a4;  As[5] = a5; Ag[5] = a5;
    }

    if (tid < D) {
        float s = 0.f;
        for (int t = 0; t < LQ; t++) s += qe[t * D + tid];
        Sq[tid] = s;
        xbq[0][tid] = qe[0 * D + tid];
        xbq[1][tid] = qe[1 * D + tid];
        xbq[2][tid] = qe[2 * D + tid];
        xbq[3][tid] = qe[(LQ - 3) * D + tid];
        xbq[4][tid] = qe[(LQ - 2) * D + tid];
        xbq[5][tid] = qe[(LQ - 1) * D + tid];
    }
    __syncthreads();

    if (tid < 32) {
        const int o = tid;
        const float invLq3 = 1.f / (float)(LQ + 3);
        float q1 = 0.f, Tv = 0.f;
        if (o < D) {
            float ds = 0.f, bc = 0.f;
            for (int j = 0; j < D; j++) ds += sW1[o * D + j] * Sq[j];
            for (int j = 0; j < D; j++) {
                const float* A = sA + (o * D + j) * 6;
                #pragma unroll
                for (int m = 0; m < 6; m++) bc += A[m] * xbq[m][j];
            }
            q1 = b1[o] + ds * invLq3;
            Tv = (float)LQ * b1[o] + ds - 0.25f * bc;
        }
        Tq[o] = Tv;
        __syncwarp();

        float q2 = 0.f;
        if (o < D) {
            float d2 = 0.f;
            for (int j = 0; j < D; j++) d2 += sW2[o * D + j] * Tq[j];
            q2 = b2[o] + d2 * invLq3;
            g_qraw[o] = Sq[o];
            g_q1g[o] = q1;
            g_q2g[o] = q2;
        }
        __syncwarp();

        float n0 = (o < D) ? Sq[o] * Sq[o] : 0.f;
        float n1 = q1 * q1;
        float n2 = q2 * q2;
        #pragma unroll
        for (int off = 16; off; off >>= 1) {
            n0 += __shfl_down_sync(0xffffffffu, n0, off);
            n1 += __shfl_down_sync(0xffffffffu, n1, off);
            n2 += __shfl_down_sync(0xffffffffu, n2, off);
        }
        if (o == 0) {
            g_inv_nraw = rsqrtf(n0);
            g_inv_n1 = rsqrtf(n1);
            g_inv_n2 = rsqrtf(n2);
        }
    }
}

// ---------------------------------------------------------------------------
// Fused kernel: stream column sums (NO atomics) + per-sentence tail math.
// One block per sentence. Channel of smem slot k = 4*tid+c is exactly k % 30.
// ---------------------------------------------------------------------------
#define TPB 480

__global__ __launch_bounds__(TPB, 4) void fused_kernel(
    const float* __restrict__ se, const float* __restrict__ gaf,
    const int* __restrict__ labels,
    const float* __restrict__ b1, const float* __restrict__ b2,
    const float* __restrict__ lw, const float* __restrict__ lb,
    float* __restrict__ out)
{
    __shared__ float sW1[D * D], sW2[D * D], sA[D * D * 6];
    __shared__ float4 part4[TPB];
    __shared__ float S[32], xb[6][32], T[32];
    __shared__ int last;

    const int n = blockIdx.x;
    const int tid = threadIdx.x;

    // Stage tables (L2-hot after prep)
    for (int i = tid; i < D * D; i += TPB) { sW1[i] = g_W1sum[i]; sW2[i] = g_W2sum[i]; }
    for (int i = tid; i < D * D * 6; i += TPB) sA[i] = g_A1[i];

    // Boundary rows
    if (tid < 6 * D) {
        int m = tid / D, j = tid % D;
        int t = (m < 3) ? m : (L - 6 + m);  // 0,1,2,509,510,511
        xb[m][j] = se[(size_t)n * (L * D) + (size_t)t * D + j];
    }

    // Stream [512,30] tile as 3840 float4s, 8 per thread, fully independent
    const float4* p = reinterpret_cast<const float4*>(se) + (size_t)n * (L * D / 4);
    float4 acc = make_float4(0.f, 0.f, 0.f, 0.f);
    #pragma unroll
    for (int it = 0; it < (L * D / 4) / TPB; it++) {
        float4 v = __ldcs(p + tid + TPB * it);
        acc.x += v.x; acc.y += v.y; acc.z += v.z; acc.w += v.w;
    }
    part4[tid] = acc;
    __syncthreads();

    // Deterministic channel reduce: slot k holds channel k % 30
    if (tid < 32) {
        const int o = tid;
        float s = 0.f;
        if (o < D) {
            const float* part = reinterpret_cast<const float*>(part4);
            #pragma unroll
            for (int k = 0; k < (TPB * 4) / D; k++)   // 64 values, stride 30
                s += part[o + D * k];
        }
        S[o] = s;
        __syncwarp();

        const float inv515 = 1.f / (float)(L + 3);
        float s1 = 0.f, Tv = 0.f;
        if (o < D) {
            float ds = 0.f, bc = 0.f;
            for (int j = 0; j < D; j++) ds += sW1[o * D + j] * S[j];
            for (int j = 0; j < D; j++) {
                const float* A = sA + (o * D + j) * 6;
                #pragma unroll
                for (int m = 0; m < 6; m++) bc += A[m] * xb[m][j];
            }
            s1 = b1[o] + ds * inv515;
            Tv = (float)L * b1[o] + ds - 0.25f * bc;
        }
        T[o] = Tv;
        __syncwarp();

        float s2 = 0.f;
        if (o < D) {
            float d2 = 0.f;
            for (int j = 0; j < D; j++) d2 += sW2[o * D + j] * T[j];
            s2 = b2[o] + d2 * inv515;
        }

        float qr = 0.f, q1v = 0.f, q2v = 0.f;
        if (o < D) { qr = g_qraw[o]; q1v = g_q1g[o]; q2v = g_q2g[o]; }

        float p0 = s * qr, p1 = s * q2v, p2 = s * s;
        float p3 = s1 * q1v, p4 = s1 * s1, p5 = s2 * q2v, p6 = s2 * s2;
        #pragma unroll
        for (int off = 16; off; off >>= 1) {
            p0 += __shfl_down_sync(0xffffffffu, p0, off);
            p1 += __shfl_down_sync(0xffffffffu, p1, off);
            p2 += __shfl_down_sync(0xffffffffu, p2, off);
            p3 += __shfl_down_sync(0xffffffffu, p3, off);
            p4 += __shfl_down_sync(0xffffffffu, p4, off);
            p5 += __shfl_down_sync(0xffffffffu, p5, off);
            p6 += __shfl_down_sync(0xffffffffu, p6, off);
        }
        if (o == 0) {
            float inv_nS = rsqrtf(p2);
            float sim1 = (n == 0) ? (p0 * g_inv_nraw * inv_nS)
                                  : (p1 * g_inv_n2 * inv_nS);
            float sim2 = p3 * rsqrtf(p4) * g_inv_n1;
            float sim3 = p5 * rsqrtf(p6) * g_inv_n2;

            const float* g = gaf + (size_t)n * AF;
            float l0 = lb[0] + lw[0] * sim1 + lw[1] * sim2 + lw[2] * sim3;
            float l1 = lb[1] + lw[13] * sim1 + lw[14] * sim2 + lw[15] * sim3;
            #pragma unroll
            for (int f = 0; f < AF; f++) {
                float gv = g[f];
                l0 += lw[3 + f] * gv;
                l1 += lw[16 + f] * gv;
            }
            float mx = fmaxf(l0, l1);
            float lse = mx + logf(expf(l0 - mx) + expf(l1 - mx));
            float lp0 = l0 - lse, lp1 = l1 - lse;
            float e0 = expf(lp0), e1 = expf(lp1);
            out[1 + n] = e1 / (e0 + e1);
            int lab = labels[n];
            g_costs[n] = -(lab ? lp1 : lp0);
        }
    }

    // Last block folds the deterministic cost reduction
    __syncthreads();
    if (tid == 0) {
        __threadfence();
        int old = atomicAdd(&g_ctr, 1);
        last = (old == NSENT - 1) ? 1 : 0;
    }
    __syncthreads();
    if (last) {
        __threadfence();
        __shared__ float sm[256];
        if (tid < 256) {
            float s = 0.f;
            for (int i = tid; i < NSENT; i += 256) s += g_costs[i];
            sm[tid] = s;
        }
        __syncthreads();
        for (int w = 128; w; w >>= 1) {
            if (tid < w) sm[tid] += sm[tid + w];
            __syncthreads();
        }
        if (tid == 0) out[0] = sm[0] / (float)NSENT;
    }
}

// ---------------------------------------------------------------------------
extern "C" void kernel_launch(void* const* d_in, const int* in_sizes, int n_in,
                              void* d_out, int out_size)
{
    const float* se  = (const float*)d_in[0];  // sents_embeds [N,L,D]
    const float* qe  = (const float*)d_in[1];  // question_embeds [LQ,D]
    const float* gaf = (const float*)d_in[2];  // [N,AF]
    const int*   lab = (const int*)d_in[3];    // [N]
    const float* w1  = (const float*)d_in[4];
    const float* b1  = (const float*)d_in[5];
    const float* w2  = (const float*)d_in[6];
    const float* b2  = (const float*)d_in[7];
    const float* lw  = (const float*)d_in[8];  // [2,13]
    const float* lb  = (const float*)d_in[9];  // [2]
    float* out = (float*)d_out;                // [0]=cost, [1..N]=emit

    prep_kernel<<<1, 960>>>(qe, w1, b1, w2, b2);
    fused_kernel<<<NSENT, TPB>>>(se, gaf, lab, b1, b2, lw, lb, out);
}